// round 6
// baseline (speedup 1.0000x reference)
#include <cuda_runtime.h>
#include <cstdint>

#define FULL_MASK 0xFFFFFFFFu

constexpr int B_ = 2048;
constexpr int L_ = 2048;
constexpr int T_ = 8;
constexpr float LOG2E_F = 1.4426950408889634f;
constexpr float LN2_F   = 0.6931471805599453f;

__device__ float g_llh[B_];
__device__ int   g_count = 0;

// Single-instruction exp2 (MUFU.EX2). No fast-math flag needed.
__device__ __forceinline__ float fast_exp2(float x)
{
    float r;
    asm("ex2.approx.ftz.f32 %0, %1;" : "=f"(r) : "f"(x));
    return r;
}
__device__ __forceinline__ float fast_expe(float x)   // exp(x) = 2^(x*log2e)
{
    return fast_exp2(x * LOG2E_F);
}

// One recursion step, scaled-linear domain, xor-gather form.
// lane j holds a_j and Er[k] = exp(trans)[j^k][j].
__device__ __forceinline__ void crf_step(
    float ex, float em_t, int tag_t, const float Er[8],
    const float* s_trans, int j, bool act,
    float& a, float& num, int& s_prev)
{
    float x1 = __shfl_xor_sync(FULL_MASK, a, 1, 8);
    float x2 = __shfl_xor_sync(FULL_MASK, a, 2, 8);
    float x3 = __shfl_xor_sync(FULL_MASK, a, 3, 8);
    float x4 = __shfl_xor_sync(FULL_MASK, a, 4, 8);
    float x5 = __shfl_xor_sync(FULL_MASK, a, 5, 8);
    float x6 = __shfl_xor_sync(FULL_MASK, a, 6, 8);
    float x7 = __shfl_xor_sync(FULL_MASK, a, 7, 8);
    int   s_t = (tag_t - 1) & 7;
    float s1 = fmaf(x1, Er[1], a  * Er[0]);
    float s2 = fmaf(x3, Er[3], x2 * Er[2]);
    float s3 = fmaf(x5, Er[5], x4 * Er[4]);
    float s4 = fmaf(x7, Er[7], x6 * Er[6]);
    float s  = (s1 + s2) + (s3 + s4);
    if (act) {
        a = s * ex;
        if (s_t == j) num += s_trans[(s_prev << 3) | j] + em_t;  // gold-lane numerator
        s_prev = s_t;
    }
}

// Exact power-of-two renormalization (scale accumulator stays integer-exact).
__device__ __forceinline__ void crf_renorm(float& a, float& c)
{
    float m = a;
    m = fmaxf(m, __shfl_xor_sync(FULL_MASK, m, 1, 8));
    m = fmaxf(m, __shfl_xor_sync(FULL_MASK, m, 2, 8));
    m = fmaxf(m, __shfl_xor_sync(FULL_MASK, m, 4, 8));
    int eb = __float_as_int(m) & 0x7f800000;
    c += (float)((eb >> 23) - 127);
    a *= __int_as_float(0x7f000000 - eb);      // exact 2^{-e}
}

__global__ __launch_bounds__(64)
void crf_main(const float* __restrict__ em,
              const float* __restrict__ trans,
              const float* __restrict__ startT,
              const float* __restrict__ endT,
              const int*   __restrict__ tags,    // (B, L) int32
              float* __restrict__ out)
{
    __shared__ float s_trans[T_ * T_];
    __shared__ float s_red[2];
    __shared__ int   s_done;
    int tid = threadIdx.x;
    s_trans[tid] = trans[tid];                   // blockDim.x == 64 == T*T
    __syncthreads();

    int lane   = tid & 31;
    int j      = lane & 7;
    int warpId = (blockIdx.x * 64 + tid) >> 5;
    int b      = warpId * 4 + (lane >> 3);

    // Rotated E: Er[k] = exp(trans[j^k][j])   (coefficient for shfl_xor(a,k))
    float Er[8];
    #pragma unroll
    for (int k = 0; k < 8; k++)
        Er[k] = fast_expe(s_trans[((j ^ k) << 3) | j]);

    const float* emb = em   + (size_t)b * (L_ * T_) + j;
    const int*   tgb = tags + (size_t)b * L_;

    // t = 0 init
    int   tag0   = tgb[0];
    int   s_prev = tag0 - 1;                     // lengths >= 1024 so tag0 != 0
    float em0    = emb[0];
    float a      = fast_expe(startT[j] + em0);
    float c      = 0.0f;
    float num    = (j == s_prev) ? (startT[j] + em0) : 0.0f;

    // ---- Phase 1: t = 1..1016, all batches guaranteed active ----
    float emv[8], exv[8]; int tgv[8];
    #pragma unroll
    for (int u = 0; u < 8; u++) {
        emv[u] = emb[(1 + u) * 8];
        tgv[u] = tgb[1 + u];
        exv[u] = fast_expe(emv[u]);
    }
    int t;
    for (t = 1; t + 15 <= 1016; t += 8) {
        float emn[8], exn[8]; int tgn[8];
        #pragma unroll
        for (int u = 0; u < 8; u++) {            // prefetch next block, exp off-chain
            emn[u] = emb[(t + 8 + u) * 8];
            tgn[u] = tgb[t + 8 + u];
            exn[u] = fast_expe(emn[u]);
        }
        #pragma unroll
        for (int u = 0; u < 8; u++)
            crf_step(exv[u], emv[u], tgv[u], Er, s_trans, j, true, a, num, s_prev);
        crf_renorm(a, c);
        #pragma unroll
        for (int u = 0; u < 8; u++) { emv[u] = emn[u]; tgv[u] = tgn[u]; exv[u] = exn[u]; }
    }
    #pragma unroll
    for (int u = 0; u < 8; u++)
        crf_step(exv[u], emv[u], tgv[u], Er, s_trans, j, true, a, num, s_prev);
    crf_renorm(a, c);
    t += 8;                                      // t == 1017

    // ---- Phase 2: t = 1017..2047, group early-exit on tag==0 (mask is a prefix) ----
    bool act = true;
    for (; t < L_; t += 8) {
        float pem[8], pex[8]; int ptg[8];
        #pragma unroll
        for (int u = 0; u < 8; u++) {
            int tt = t + u;
            bool ld = act && (tt < L_);
            pem[u] = ld ? emb[tt * 8] : 0.0f;
            ptg[u] = ld ? tgb[tt] : 0;
            pex[u] = fast_expe(pem[u]);
        }
        #pragma unroll
        for (int u = 0; u < 8; u++) {
            int tt = t + u;                      // warp-uniform
            if (tt < L_) {
                bool a2 = act && (ptg[u] != 0);
                crf_step(pex[u], pem[u], ptg[u], Er, s_trans, j, a2, a, num, s_prev);
                act = a2;
            }
        }
        crf_renorm(a, c);
        if (!__ballot_sync(FULL_MASK, act)) break;
    }

    // ---- Finalize ----
    float vend = a * fast_expe(endT[j]);
    vend += __shfl_xor_sync(FULL_MASK, vend, 1, 8);
    vend += __shfl_xor_sync(FULL_MASK, vend, 2, 8);
    vend += __shfl_xor_sync(FULL_MASK, vend, 4, 8);
    float denom = (c + __log2f(vend)) * LN2_F;
    if (j == s_prev) num += endT[j];
    num += __shfl_xor_sync(FULL_MASK, num, 1, 8);
    num += __shfl_xor_sync(FULL_MASK, num, 2, 8);
    num += __shfl_xor_sync(FULL_MASK, num, 4, 8);
    if (j == 0) g_llh[b] = num - denom;

    // ---- Last block reduces (fixed order -> deterministic) ----
    __threadfence();                             // EVERY thread orders its g_llh write
    __syncthreads();                             // all block writes+fences done
    if (tid == 0) s_done = atomicAdd(&g_count, 1);
    __syncthreads();
    if (s_done == gridDim.x - 1) {
        __threadfence();                         // acquire side
        float s = 0.0f;
        for (int i = tid; i < B_; i += 64)
            s += __ldcg(&g_llh[i]);              // L2 read, fixed per-thread order
        #pragma unroll
        for (int k = 16; k > 0; k >>= 1) s += __shfl_xor_sync(FULL_MASK, s, k);
        if (lane == 0) s_red[tid >> 5] = s;
        __syncthreads();
        if (tid == 0) {
            out[0] = -(s_red[0] + s_red[1]) * (1.0f / (float)B_);
            g_count = 0;                         // reset for next graph replay
        }
    }
}

extern "C" void kernel_launch(void* const* d_in, const int* in_sizes, int n_in,
                              void* d_out, int out_size)
{
    const float* em    = (const float*)d_in[0];   // (B, L, T) f32
    const float* trans = (const float*)d_in[1];   // (T, T)    f32
    const float* st    = (const float*)d_in[2];   // (T,)      f32
    const float* en    = (const float*)d_in[3];   // (T,)      f32
    const int*   tags  = (const int*)  d_in[4];   // (B, L)    int32

    crf_main<<<256, 64>>>(em, trans, st, en, tags, (float*)d_out);
}

// round 8
// speedup vs baseline: 1.8182x; 1.8182x over previous
#include <cuda_runtime.h>
#include <cstdint>

#define FULL_MASK 0xFFFFFFFFu

constexpr int B_ = 2048;
constexpr int L_ = 2048;
constexpr int T_ = 8;
constexpr float LOG2E_F = 1.4426950408889634f;
constexpr float LN2_F   = 0.6931471805599453f;

// device scratch (no allocation allowed)
__device__ int   g_len[B_];
__device__ int   g_order[B_];
__device__ float g_alpha[B_ * 8];
__device__ float g_beta [B_ * 8];
__device__ float g_cf[B_], g_cb[B_], g_numf[B_], g_numb[B_];

__device__ __forceinline__ float fast_exp2(float x)
{
    float r;
    asm("ex2.approx.ftz.f32 %0, %1;" : "=f"(r) : "f"(x));
    return r;
}
__device__ __forceinline__ float fast_expe(float x) { return fast_exp2(x * LOG2E_F); }

// Exact power-of-two renormalization across the 8-lane group.
__device__ __forceinline__ void grp_renorm(float& a, float& c)
{
    float m = a;
    m = fmaxf(m, __shfl_xor_sync(FULL_MASK, m, 1, 8));
    m = fmaxf(m, __shfl_xor_sync(FULL_MASK, m, 2, 8));
    m = fmaxf(m, __shfl_xor_sync(FULL_MASK, m, 4, 8));
    int eb = __float_as_int(m) & 0x7f800000;
    c += (float)((eb >> 23) - 127);
    a *= __int_as_float(0x7f000000 - eb);      // exact 2^{-e}
}

// ---------------- kernel 1: sequence lengths (mask is a prefix; len in [1024,2048]) ----
__global__ void scan_len(const int* __restrict__ tags)
{
    int w    = blockIdx.x * 8 + (threadIdx.x >> 5);   // batch id, grid 256x256 -> 2048 warps
    int lane = threadIdx.x & 31;
    const int4* p = (const int4*)(tags + (size_t)w * L_ + 1024);
    int firstz = 1024;
    #pragma unroll
    for (int k = 0; k < 8; k++) {
        int4 v = p[k * 32 + lane];
        int base = (k * 32 + lane) * 4;
        if (v.w == 0) firstz = min(firstz, base + 3);
        if (v.z == 0) firstz = min(firstz, base + 2);
        if (v.y == 0) firstz = min(firstz, base + 1);
        if (v.x == 0) firstz = min(firstz, base + 0);
    }
    firstz = __reduce_min_sync(FULL_MASK, firstz);
    if (lane == 0) g_len[w] = 1024 + firstz;
}

// ---------------- kernel 2: length-sorted order via all-pairs rank (deterministic) ----
__global__ void rank_order()
{
    __shared__ int s_len[B_];
    for (int i = threadIdx.x; i < B_; i += blockDim.x) s_len[i] = g_len[i];
    __syncthreads();
    int b   = blockIdx.x * blockDim.x + threadIdx.x;   // grid 16x128 -> 2048 threads
    int myl = s_len[b];
    int r = 0;
    #pragma unroll 4
    for (int i = 0; i < B_; i++) {
        int li = s_len[i];
        r += (li < myl) || (li == myl && i < b);
    }
    g_order[r] = b;
}

// ---------------- kernel 3: main forward/backward recursions ----------------
__global__ __launch_bounds__(128)
void crf_main(const float* __restrict__ em,
              const float* __restrict__ trans,
              const float* __restrict__ startT,
              const float* __restrict__ endT,
              const int*   __restrict__ tags)
{
    __shared__ float s_trans[T_ * T_];
    int tid = threadIdx.x;
    if (tid < 64) s_trans[tid] = trans[tid];
    __syncthreads();

    int lane = tid & 31;
    int j    = lane & 7;
    int W    = blockIdx.x * 4 + (tid >> 5);            // 0..1023
    bool is_bwd = (W >= 512);
    int  idx    = is_bwd ? (W - 512) : W;

    int b   = g_order[idx * 4 + (lane >> 3)];
    int len = g_len[b];
    int mid = len >> 1;                                // fwd covers t=0..mid, bwd covers (mid, len-1]

    const float* emb = em   + (size_t)b * (L_ * T_) + j;
    const int*   tgb = tags + (size_t)b * L_;

    float emA[8], exA[8], emB[8], exB[8], emC[8], exC[8];
    int   tgA[8], tgB[8], tgC[8];

    if (!is_bwd) {
        // ======== FORWARD: alpha_t = ex_t ⊙ (E^T alpha_{t-1}),  t = 1..mid ========
        float Er[8];
        #pragma unroll
        for (int k = 0; k < 8; k++) Er[k] = fast_expe(s_trans[((j ^ k) << 3) | j]);

        int lim  = mid;
        int m_hi = __reduce_max_sync(FULL_MASK, mid);

        int   s_prev = tgb[0] - 1;                     // len>=1024 => tag0 != 0
        float em0    = emb[0];
        float a      = fast_expe(startT[j] + em0);
        float c      = 0.0f;
        float num    = (j == s_prev) ? (startT[j] + em0) : 0.0f;

        #pragma unroll
        for (int u = 0; u < 8; u++) { emA[u] = emb[(1 + u) * 8]; tgA[u] = tgb[1 + u]; exA[u] = fast_expe(emA[u]); }
        #pragma unroll
        for (int u = 0; u < 8; u++) { emB[u] = emb[(9 + u) * 8]; tgB[u] = tgb[9 + u]; exB[u] = fast_expe(emB[u]); }

        for (int t = 1; t <= m_hi; t += 8) {
            #pragma unroll
            for (int u = 0; u < 8; u++) {              // prefetch 2 blocks ahead (<=1047 < L_)
                int q = t + 16 + u;
                emC[u] = emb[q * 8]; tgC[u] = tgb[q]; exC[u] = fast_expe(emC[u]);
            }
            #pragma unroll
            for (int u = 0; u < 8; u++) {
                int tt = t + u;
                float x1 = __shfl_xor_sync(FULL_MASK, a, 1, 8);
                float x2 = __shfl_xor_sync(FULL_MASK, a, 2, 8);
                float x3 = __shfl_xor_sync(FULL_MASK, a, 3, 8);
                float x4 = __shfl_xor_sync(FULL_MASK, a, 4, 8);
                float x5 = __shfl_xor_sync(FULL_MASK, a, 5, 8);
                float x6 = __shfl_xor_sync(FULL_MASK, a, 6, 8);
                float x7 = __shfl_xor_sync(FULL_MASK, a, 7, 8);
                float s1 = fmaf(x1, Er[1], a  * Er[0]);
                float s2 = fmaf(x3, Er[3], x2 * Er[2]);
                float s3 = fmaf(x5, Er[5], x4 * Er[4]);
                float s4 = fmaf(x7, Er[7], x6 * Er[6]);
                float s  = (s1 + s2) + (s3 + s4);
                bool act = (tt <= lim);
                int  s_t = tgA[u] - 1;
                if (act) {
                    a = s * exA[u];
                    if (j == s_t) num += s_trans[(s_prev << 3) | j] + emA[u];
                    s_prev = s_t;
                }
            }
            grp_renorm(a, c);
            #pragma unroll
            for (int u = 0; u < 8; u++) {
                emA[u] = emB[u]; exA[u] = exB[u]; tgA[u] = tgB[u];
                emB[u] = emC[u]; exB[u] = exC[u]; tgB[u] = tgC[u];
            }
        }
        num += __shfl_xor_sync(FULL_MASK, num, 1, 8);
        num += __shfl_xor_sync(FULL_MASK, num, 2, 8);
        num += __shfl_xor_sync(FULL_MASK, num, 4, 8);
        g_alpha[b * 8 + j] = a;
        if (j == 0) { g_cf[b] = c; g_numf[b] = num; }
    } else {
        // ======== BACKWARD: beta_{t-1} = E (ex_t ⊙ beta_t),  t = len-1 .. mid+1 ========
        float ErR[8];
        #pragma unroll
        for (int k = 0; k < 8; k++) ErR[k] = fast_expe(s_trans[(j << 3) | (j ^ k)]);

        float endj = endT[j];
        float beta = fast_expe(endj);
        float c = 0.0f, num = 0.0f;
        int   s_succ = 0;

        int t0   = __reduce_max_sync(FULL_MASK, len) - 1;
        int tmin = __reduce_min_sync(FULL_MASK, mid) + 1;

        #pragma unroll
        for (int u = 0; u < 8; u++) { int q = t0 - u;     emA[u] = emb[q * 8]; tgA[u] = tgb[q]; exA[u] = fast_expe(emA[u]); }
        #pragma unroll
        for (int u = 0; u < 8; u++) { int q = t0 - 8 - u; emB[u] = emb[q * 8]; tgB[u] = tgb[q]; exB[u] = fast_expe(emB[u]); }

        for (int t = t0; t >= tmin; t -= 8) {
            #pragma unroll
            for (int u = 0; u < 8; u++) {              // prefetch 2 blocks ahead (>= tmin-23 >= 490)
                int q = t - 16 - u;
                emC[u] = emb[q * 8]; tgC[u] = tgb[q]; exC[u] = fast_expe(emC[u]);
            }
            #pragma unroll
            for (int u = 0; u < 8; u++) {
                int tt = t - u;
                float p  = beta * exA[u];
                float x1 = __shfl_xor_sync(FULL_MASK, p, 1, 8);
                float x2 = __shfl_xor_sync(FULL_MASK, p, 2, 8);
                float x3 = __shfl_xor_sync(FULL_MASK, p, 3, 8);
                float x4 = __shfl_xor_sync(FULL_MASK, p, 4, 8);
                float x5 = __shfl_xor_sync(FULL_MASK, p, 5, 8);
                float x6 = __shfl_xor_sync(FULL_MASK, p, 6, 8);
                float x7 = __shfl_xor_sync(FULL_MASK, p, 7, 8);
                float s1 = fmaf(x1, ErR[1], p  * ErR[0]);
                float s2 = fmaf(x3, ErR[3], x2 * ErR[2]);
                float s3 = fmaf(x5, ErR[5], x4 * ErR[4]);
                float s4 = fmaf(x7, ErR[7], x6 * ErR[6]);
                float s  = (s1 + s2) + (s3 + s4);
                bool act = (tt > mid) && (tt < len);
                int  s_t = tgA[u] - 1;
                if (act) {
                    beta = s;
                    if (j == s_t)
                        num += emA[u] + ((tt == len - 1) ? endj : s_trans[(j << 3) | s_succ]);
                    s_succ = s_t;
                }
            }
            grp_renorm(beta, c);
            #pragma unroll
            for (int u = 0; u < 8; u++) {
                emA[u] = emB[u]; exA[u] = exB[u]; tgA[u] = tgB[u];
                emB[u] = emC[u]; exB[u] = exC[u]; tgB[u] = tgC[u];
            }
        }
        // missing transition pair (s_mid -> s_{mid+1}); s_succ == s_{mid+1} here
        int s_m = tgb[mid] - 1;
        if (j == s_m) num += s_trans[(j << 3) | s_succ];

        num += __shfl_xor_sync(FULL_MASK, num, 1, 8);
        num += __shfl_xor_sync(FULL_MASK, num, 2, 8);
        num += __shfl_xor_sync(FULL_MASK, num, 4, 8);
        g_beta[b * 8 + j] = beta;
        if (j == 0) { g_cb[b] = c; g_numb[b] = num; }
    }
}

// ---------------- kernel 4: combine halves + deterministic mean ----------------
__global__ void crf_combine(float* __restrict__ out)
{
    __shared__ float sb[128];
    int tid = threadIdx.x;                             // 1024 threads
    int j   = tid & 7;
    float acc = 0.0f;
    #pragma unroll 1
    for (int it = 0; it < 16; it++) {
        int b = (tid >> 3) + it * 128;
        float v = g_alpha[b * 8 + j] * g_beta[b * 8 + j];
        v += __shfl_xor_sync(FULL_MASK, v, 1, 8);
        v += __shfl_xor_sync(FULL_MASK, v, 2, 8);
        v += __shfl_xor_sync(FULL_MASK, v, 4, 8);
        if (j == 0) {
            float llh = g_numf[b] + g_numb[b]
                      - LN2_F * (g_cf[b] + g_cb[b] + __log2f(v));
            acc += llh;                                // fixed per-thread order
        }
    }
    if (j == 0) sb[tid >> 3] = acc;
    __syncthreads();
    if (tid < 64) sb[tid] += sb[tid + 64];
    __syncthreads();
    if (tid < 32) {
        float v2 = sb[tid] + sb[tid + 32];
        #pragma unroll
        for (int k = 16; k > 0; k >>= 1) v2 += __shfl_xor_sync(FULL_MASK, v2, k);
        if (tid == 0) out[0] = -v2 * (1.0f / (float)B_);
    }
}

extern "C" void kernel_launch(void* const* d_in, const int* in_sizes, int n_in,
                              void* d_out, int out_size)
{
    const float* em    = (const float*)d_in[0];   // (B, L, T) f32
    const float* trans = (const float*)d_in[1];   // (T, T)    f32
    const float* st    = (const float*)d_in[2];   // (T,)      f32
    const float* en    = (const float*)d_in[3];   // (T,)      f32
    const int*   tags  = (const int*)  d_in[4];   // (B, L)    int32

    scan_len  <<<256, 256>>>(tags);
    rank_order<<<16, 128>>>();
    crf_main  <<<256, 128>>>(em, trans, st, en, tags);
    crf_combine<<<1, 1024>>>((float*)d_out);
}

// round 9
// speedup vs baseline: 2.1668x; 1.1917x over previous
#include <cuda_runtime.h>
#include <cstdint>

#define FULL_MASK 0xFFFFFFFFu

constexpr int B_ = 2048;
constexpr int L_ = 2048;
constexpr int T_ = 8;
constexpr float LOG2E_F = 1.4426950408889634f;
constexpr float LN2_F   = 0.6931471805599453f;

// device scratch (no allocation allowed)
__device__ int   g_len[B_];
__device__ int   g_order[B_];
__device__ __align__(16) float g_alpha[B_ * 8];
__device__ __align__(16) float g_beta [B_ * 8];
__device__ float g_cf[B_], g_cb[B_], g_numf[B_], g_numb[B_];

__device__ __forceinline__ float fast_exp2(float x)
{
    float r;
    asm("ex2.approx.ftz.f32 %0, %1;" : "=f"(r) : "f"(x));
    return r;
}
__device__ __forceinline__ float fast_expe(float x) { return fast_exp2(x * LOG2E_F); }

__device__ __forceinline__ void l2_prefetch(const void* p)
{
    asm volatile("prefetch.global.L2 [%0];" :: "l"(p));
}

// Cheap exact power-of-two renorm: scale group by 2^-e(lane0). Post-mixing
// spread of alpha components is <= ~2^12, growth per 8 steps <= ~2^90 -> safe.
__device__ __forceinline__ void grp_renorm_l0(float& a, float& c)
{
    float a0 = __shfl_sync(FULL_MASK, a, 0, 8);
    int eb = __float_as_int(a0) & 0x7f800000;
    c += (float)((eb >> 23) - 127);
    a *= __int_as_float(0x7f000000 - eb);      // exact 2^{-e}
}

// ---------------- kernel 1: sequence lengths (mask is a prefix; len in [1024,2048]) ----
__global__ void scan_len(const int* __restrict__ tags)
{
    int w    = blockIdx.x * 8 + (threadIdx.x >> 5);   // batch id, grid 256x256 -> 2048 warps
    int lane = threadIdx.x & 31;
    const int4* p = (const int4*)(tags + (size_t)w * L_ + 1024);
    int firstz = 1024;
    #pragma unroll
    for (int k = 0; k < 8; k++) {
        int4 v = p[k * 32 + lane];
        int base = (k * 32 + lane) * 4;
        if (v.w == 0) firstz = min(firstz, base + 3);
        if (v.z == 0) firstz = min(firstz, base + 2);
        if (v.y == 0) firstz = min(firstz, base + 1);
        if (v.x == 0) firstz = min(firstz, base + 0);
    }
    firstz = __reduce_min_sync(FULL_MASK, firstz);
    if (lane == 0) g_len[w] = 1024 + firstz;
}

// ---------------- kernel 2: length-sorted order via all-pairs rank (deterministic) ----
__global__ void rank_order()
{
    __shared__ int s_len[B_];
    for (int i = threadIdx.x; i < B_; i += blockDim.x) s_len[i] = g_len[i];
    __syncthreads();
    int b   = blockIdx.x * blockDim.x + threadIdx.x;   // grid 16x128 -> 2048 threads
    int myl = s_len[b];
    int r = 0;
    #pragma unroll 8
    for (int i = 0; i < B_; i++) {
        int li = s_len[i];
        r += (li < myl) || (li == myl && i < b);
    }
    g_order[r] = b;
}

// ---------------- kernel 3: main forward/backward recursions ----------------
__global__ __launch_bounds__(128)
void crf_main(const float* __restrict__ em,
              const float* __restrict__ trans,
              const float* __restrict__ startT,
              const float* __restrict__ endT,
              const int*   __restrict__ tags)
{
    __shared__ float s_trans[T_ * T_];
    int tid = threadIdx.x;
    if (tid < 64) s_trans[tid] = trans[tid];
    __syncthreads();

    int lane = tid & 31;
    int j    = lane & 7;
    int W    = blockIdx.x * 4 + (tid >> 5);            // 0..1023
    bool is_bwd = (W >= 512);
    int  idx    = is_bwd ? (W - 512) : W;

    int b   = g_order[idx * 4 + (lane >> 3)];
    int len = g_len[b];
    int mid = len >> 1;                                // fwd: t=0..mid, bwd: (mid, len-1]

    const float* emb = em   + (size_t)b * (L_ * T_) + j;
    const int*   tgb = tags + (size_t)b * L_;

    // double buffers (40 regs total) -- fully static indexing, must stay in regs
    float emA[8], exA[8], emB[8];
    int   tgA[8], tgB[8];

    if (!is_bwd) {
        // ======== FORWARD: alpha_t = ex_t ⊙ (E^T alpha_{t-1}),  t = 1..mid ========
        float Er[8];
        #pragma unroll
        for (int k = 0; k < 8; k++) Er[k] = fast_expe(s_trans[((j ^ k) << 3) | j]);

        int lim  = mid;
        int m_hi = __reduce_max_sync(FULL_MASK, mid);

        int   s_prev = tgb[0] - 1;                     // len>=1024 => tag0 != 0
        float em0    = emb[0];
        float a      = fast_expe(startT[j] + em0);
        float c      = 0.0f;
        float num    = (j == s_prev) ? (startT[j] + em0) : 0.0f;

        #pragma unroll
        for (int u = 0; u < 8; u++) { emA[u] = emb[(1 + u) * 8]; tgA[u] = tgb[1 + u]; }
        #pragma unroll
        for (int u = 0; u < 8; u++) { emB[u] = emb[(9 + u) * 8]; tgB[u] = tgb[9 + u]; }
        #pragma unroll
        for (int u = 0; u < 8; u++) exA[u] = fast_expe(emA[u]);

        for (int t = 1; t <= m_hi; t += 8) {
            l2_prefetch(&emb[(t + 24 + j) * 8]);       // 8 lanes span the 256B block region
            if (j == 0) l2_prefetch(&tgb[t + 24]);
            #pragma unroll
            for (int u = 0; u < 8; u++) {
                int tt = t + u;
                float x1 = __shfl_xor_sync(FULL_MASK, a, 1, 8);
                float x2 = __shfl_xor_sync(FULL_MASK, a, 2, 8);
                float x3 = __shfl_xor_sync(FULL_MASK, a, 3, 8);
                float x4 = __shfl_xor_sync(FULL_MASK, a, 4, 8);
                float x5 = __shfl_xor_sync(FULL_MASK, a, 5, 8);
                float x6 = __shfl_xor_sync(FULL_MASK, a, 6, 8);
                float x7 = __shfl_xor_sync(FULL_MASK, a, 7, 8);
                float s1 = fmaf(x1, Er[1], a  * Er[0]);
                float s2 = fmaf(x3, Er[3], x2 * Er[2]);
                float s3 = fmaf(x5, Er[5], x4 * Er[4]);
                float s4 = fmaf(x7, Er[7], x6 * Er[6]);
                float s  = (s1 + s2) + (s3 + s4);
                bool act = (tt <= lim);
                int  s_t = tgA[u] - 1;
                if (act) {
                    a = s * exA[u];
                    if (j == s_t) num += s_trans[(s_prev << 3) | j] + emA[u];
                    s_prev = s_t;
                }
            }
            grp_renorm_l0(a, c);
            #pragma unroll
            for (int u = 0; u < 8; u++) { emA[u] = emB[u]; tgA[u] = tgB[u]; }
            #pragma unroll
            for (int u = 0; u < 8; u++) {              // load block t+16 (max 1047 < 2048)
                emB[u] = emb[(t + 16 + u) * 8]; tgB[u] = tgb[t + 16 + u];
            }
            #pragma unroll
            for (int u = 0; u < 8; u++) exA[u] = fast_expe(emA[u]);
        }
        num += __shfl_xor_sync(FULL_MASK, num, 1, 8);
        num += __shfl_xor_sync(FULL_MASK, num, 2, 8);
        num += __shfl_xor_sync(FULL_MASK, num, 4, 8);
        g_alpha[b * 8 + j] = a;
        if (j == 0) { g_cf[b] = c; g_numf[b] = num; }
    } else {
        // ======== BACKWARD: beta_{t-1} = E (ex_t ⊙ beta_t),  t = len-1 .. mid+1 ========
        float ErR[8];
        #pragma unroll
        for (int k = 0; k < 8; k++) ErR[k] = fast_expe(s_trans[(j << 3) | (j ^ k)]);

        float endj = endT[j];
        float beta = fast_expe(endj);
        float c = 0.0f, num = 0.0f;
        int   s_succ = 0;

        int t0   = __reduce_max_sync(FULL_MASK, len) - 1;
        int tmin = __reduce_min_sync(FULL_MASK, mid) + 1;

        #pragma unroll
        for (int u = 0; u < 8; u++) { int q = t0 - u;     emA[u] = emb[q * 8]; tgA[u] = tgb[q]; }
        #pragma unroll
        for (int u = 0; u < 8; u++) { int q = t0 - 8 - u; emB[u] = emb[q * 8]; tgB[u] = tgb[q]; }
        #pragma unroll
        for (int u = 0; u < 8; u++) exA[u] = fast_expe(emA[u]);

        for (int t = t0; t >= tmin; t -= 8) {
            l2_prefetch(&emb[(t - 24 - j) * 8]);       // min index (tmin-31)*8 >= 0
            if (j == 0) l2_prefetch(&tgb[t - 24]);
            #pragma unroll
            for (int u = 0; u < 8; u++) {
                int tt = t - u;
                float p  = beta * exA[u];
                float x1 = __shfl_xor_sync(FULL_MASK, p, 1, 8);
                float x2 = __shfl_xor_sync(FULL_MASK, p, 2, 8);
                float x3 = __shfl_xor_sync(FULL_MASK, p, 3, 8);
                float x4 = __shfl_xor_sync(FULL_MASK, p, 4, 8);
                float x5 = __shfl_xor_sync(FULL_MASK, p, 5, 8);
                float x6 = __shfl_xor_sync(FULL_MASK, p, 6, 8);
                float x7 = __shfl_xor_sync(FULL_MASK, p, 7, 8);
                float s1 = fmaf(x1, ErR[1], p  * ErR[0]);
                float s2 = fmaf(x3, ErR[3], x2 * ErR[2]);
                float s3 = fmaf(x5, ErR[5], x4 * ErR[4]);
                float s4 = fmaf(x7, ErR[7], x6 * ErR[6]);
                float s  = (s1 + s2) + (s3 + s4);
                bool act = (tt > mid) && (tt < len);
                int  s_t = tgA[u] - 1;
                if (act) {
                    beta = s;
                    if (j == s_t)
                        num += emA[u] + ((tt == len - 1) ? endj : s_trans[(j << 3) | s_succ]);
                    s_succ = s_t;
                }
            }
            grp_renorm_l0(beta, c);
            #pragma unroll
            for (int u = 0; u < 8; u++) { emA[u] = emB[u]; tgA[u] = tgB[u]; }
            #pragma unroll
            for (int u = 0; u < 8; u++) {              // load block t-16.. (min q >= 490-7 > 0)
                int q = t - 16 - u;
                emB[u] = emb[q * 8]; tgB[u] = tgb[q];
            }
            #pragma unroll
            for (int u = 0; u < 8; u++) exA[u] = fast_expe(emA[u]);
        }
        // missing transition pair (s_mid -> s_{mid+1}); s_succ == s_{mid+1} here
        int s_m = tgb[mid] - 1;
        if (j == s_m) num += s_trans[(j << 3) | s_succ];

        num += __shfl_xor_sync(FULL_MASK, num, 1, 8);
        num += __shfl_xor_sync(FULL_MASK, num, 2, 8);
        num += __shfl_xor_sync(FULL_MASK, num, 4, 8);
        g_beta[b * 8 + j] = beta;
        if (j == 0) { g_cb[b] = c; g_numb[b] = num; }
    }
}

// ---------------- kernel 4: combine halves + deterministic mean ----------------
__global__ void crf_combine(float* __restrict__ out)
{
    __shared__ float sb[256];
    int tid = threadIdx.x;                             // 256 threads, 1 block
    float acc = 0.0f;
    #pragma unroll 1
    for (int it = 0; it < 8; it++) {
        int b = tid + it * 256;                        // fixed per-thread order
        const float4* pa = (const float4*)&g_alpha[b * 8];
        const float4* pb = (const float4*)&g_beta [b * 8];
        float4 a0 = pa[0], a1 = pa[1], b0 = pb[0], b1 = pb[1];
        float v = a0.x * b0.x + a0.y * b0.y + a0.z * b0.z + a0.w * b0.w
                + a1.x * b1.x + a1.y * b1.y + a1.z * b1.z + a1.w * b1.w;
        acc += g_numf[b] + g_numb[b]
             - LN2_F * (g_cf[b] + g_cb[b] + __log2f(v));
    }
    sb[tid] = acc;
    __syncthreads();
    for (int k = 128; k > 0; k >>= 1) {
        if (tid < k) sb[tid] += sb[tid + k];
        __syncthreads();
    }
    if (tid == 0) out[0] = -sb[0] * (1.0f / (float)B_);
}

extern "C" void kernel_launch(void* const* d_in, const int* in_sizes, int n_in,
                              void* d_out, int out_size)
{
    const float* em    = (const float*)d_in[0];   // (B, L, T) f32
    const float* trans = (const float*)d_in[1];   // (T, T)    f32
    const float* st    = (const float*)d_in[2];   // (T,)      f32
    const float* en    = (const float*)d_in[3];   // (T,)      f32
    const int*   tags  = (const int*)  d_in[4];   // (B, L)    int32

    scan_len   <<<256, 256>>>(tags);
    rank_order <<<16, 128>>>();
    crf_main   <<<256, 128>>>(em, trans, st, en, tags);
    crf_combine<<<1, 256>>>((float*)d_out);
}